// round 8
// baseline (speedup 1.0000x reference)
#include <cuda_runtime.h>
#include <cstdint>

#define Bb   4
#define Nn   2048
#define Hh   8
#define HG   4            // heads per CTA in gat_mma
#define IN_D 128
#define Oo   32
#define LOG2E 1.44269504f

#define BI   64           // rows per CTA (MMA M)
#define KC   16           // j per chunk (MMA K per chunk)
#define NCH  (Nn/KC)      // 128 chunks

// ---------------- scratch (device globals) ----------------------------------
__device__ float g_Wh[(size_t)Bb*Hh*Nn*Oo];   // [b][h][n][o], tf32-rounded
__device__ float g_asrc[(size_t)Bb*Hh*Nn];
__device__ float g_adst[(size_t)Bb*Hh*Nn];
__device__ float g_maxd[Bb*Hh];

__device__ __forceinline__ float ex2f_fast(float x) {
    float r; asm("ex2.approx.ftz.f32 %0, %1;" : "=f"(r) : "f"(x)); return r;
}
__device__ __forceinline__ float tf32_rn(float x) {
    uint32_t r; asm("cvt.rna.tf32.f32 %0, %1;" : "=r"(r) : "f"(x));
    return __uint_as_float(r);
}
__device__ __forceinline__ void cp_async16(uint32_t dst, const void* src) {
    asm volatile("cp.async.cg.shared.global [%0], [%1], 16;"
                 :: "r"(dst), "l"(src));
}

// ============================================================================
// Kernel 1: Wh (tf32-rounded, [b][h][n][o]) + alpha_src/alpha_dst
// grid (Nn/32, Hh, Bb) = 2048 CTAs, 256 threads, ONE head per CTA.
// ============================================================================
__global__ __launch_bounds__(256, 4) void wh_kernel(
    const float* __restrict__ x, const float* __restrict__ W,
    const float* __restrict__ a_src, const float* __restrict__ a_dst)
{
    __shared__ __align__(16) float x_sm[32][IN_D];      // 16 KB
    __shared__ __align__(16) float w_sm[IN_D * Oo];     // 16 KB

    const int b   = blockIdx.z;
    const int h   = blockIdx.y;
    const int n0  = blockIdx.x * 32;
    const int tid = threadIdx.x;
    const int lane = tid & 31;       // = o
    const int wq   = tid >> 5;       // warp -> 4 rows

    {   // x tile: 32*128 floats
        const float4* xg = (const float4*)(x + ((size_t)b*Nn + n0)*IN_D);
        float4* xs = (float4*)&x_sm[0][0];
        #pragma unroll
        for (int k = 0; k < 4; ++k) xs[tid + k*256] = xg[tid + k*256];
    }
    {   // W[h]: 128*32 floats
        const float4* wg = (const float4*)(W + (size_t)h*IN_D*Oo);
        float4* ws = (float4*)w_sm;
        #pragma unroll
        for (int k = 0; k < 4; ++k) ws[tid + k*256] = wg[tid + k*256];
    }
    __syncthreads();

    float acc[4] = {0.f, 0.f, 0.f, 0.f};
    #pragma unroll 8
    for (int f4 = 0; f4 < IN_D/4; ++f4) {
        float4 xv[4];
        #pragma unroll
        for (int r = 0; r < 4; ++r)
            xv[r] = ((const float4*)&x_sm[wq*4 + r][0])[f4];
        #pragma unroll
        for (int u = 0; u < 4; ++u) {
            float wv = w_sm[(f4*4 + u)*Oo + lane];
            acc[0] += (u==0?xv[0].x:u==1?xv[0].y:u==2?xv[0].z:xv[0].w) * wv;
            acc[1] += (u==0?xv[1].x:u==1?xv[1].y:u==2?xv[1].z:xv[1].w) * wv;
            acc[2] += (u==0?xv[2].x:u==1?xv[2].y:u==2?xv[2].z:xv[2].w) * wv;
            acc[3] += (u==0?xv[3].x:u==1?xv[3].y:u==2?xv[3].z:xv[3].w) * wv;
        }
    }

    const float asv = a_src[h*Oo + lane];
    const float adv = a_dst[h*Oo + lane];
    #pragma unroll
    for (int r = 0; r < 4; ++r) {
        int n = n0 + wq*4 + r;
        g_Wh[(((size_t)b*Hh + h)*Nn + n)*Oo + lane] = tf32_rn(acc[r]);
        float ps = acc[r] * asv;
        float pd = acc[r] * adv;
        #pragma unroll
        for (int s = 16; s > 0; s >>= 1) {
            ps += __shfl_xor_sync(~0u, ps, s);
            pd += __shfl_xor_sync(~0u, pd, s);
        }
        if (lane == 0) {
            g_asrc[((size_t)b*Hh + h)*Nn + n] = ps;
            g_adst[((size_t)b*Hh + h)*Nn + n] = pd;
        }
    }
}

// ============================================================================
// Kernel 2: per-(b,h) max of alpha_dst
// ============================================================================
__global__ __launch_bounds__(256) void maxd_kernel()
{
    const int bh  = blockIdx.x;
    const int tid = threadIdx.x;
    float m = -1e30f;
    for (int n = tid; n < Nn; n += 256)
        m = fmaxf(m, g_adst[(size_t)bh*Nn + n]);
    __shared__ float red[256];
    red[tid] = m;
    __syncthreads();
    for (int s = 128; s > 0; s >>= 1) {
        if (tid < s) red[tid] = fmaxf(red[tid], red[tid + s]);
        __syncthreads();
    }
    if (tid == 0) g_maxd[bh] = red[0];
}

// ============================================================================
// Kernel 3: fused masked-softmax + AV via mma.sync.m16n8k8.tf32
// grid (32, 2, 4) = 256 CTAs; 256 threads; 4 heads per CTA; 2 CTAs/SM.
// SINGLE __syncthreads per chunk:
//   phase A: STS ej(c+1); p-gen(c) -> p[c&1]
//   sync(c)
//   phase B: cp.async wh(c+1); wait_group; mma(c); LDG adj/adst prefetch
// Safety: one barrier/iter => no two warps ever in different phase-B's;
// p[c&1] rewritten only at A(c+2) (after sync(c+1) > everyone's mma(c));
// cp.async into wh[(c+1)&1] can't race mma(c-1) (sync(c) separates);
// ej[(c+1)&1] STS can't race A(c-1) reads (sync(c-1) separates).
// SMEM (dynamic, 63488 B):
//   p_sm  [2][4][64][20]   words 0..10239
//   wh_sm [2][4][16][40]   words 10240..15359
//   ej_sm [2][4][16][2]    words 15360..15615
//   z_sm  [4][64]          words 15616..15871
// ============================================================================
__global__ __launch_bounds__(256, 2) void gat_mma(const float* __restrict__ adj,
                                                  float* __restrict__ out)
{
    extern __shared__ float sm[];
    float* p_sm  = sm;
    float* wh_sm = sm + 10240;
    float* ej_sm = sm + 15360;
    float* z_sm  = sm + 15616;

    const int tid  = threadIdx.x;
    const int lane = tid & 31;
    const int wid  = tid >> 5;       // 0..7
    const int hL   = wid >> 1;       // local mma head 0..3
    const int mh   = wid & 1;        // row half
    const int b    = blockIdx.z;
    const int h0   = blockIdx.y * HG;
    const int i0   = blockIdx.x * BI;
    const int ith  = tid >> 2;       // p-gen row 0..63
    const int j4   = tid & 3;        // p-gen j-quad
    const int iglob = i0 + ith;
    const int g  = lane >> 2;
    const int t4 = lane & 3;
    const int eh = tid >> 4;         // ej-stage head (tid<64)
    const int ej = tid & 15;         // ej-stage j

    const uint32_t wh_u32 = (uint32_t)__cvta_generic_to_shared(wh_sm);

    // per-(h,i) hoisted exponentials: w = max(E1i*E1j, E2i*E2j) * mask
    float E1i[HG], E2i[HG], zacc[HG];
    #pragma unroll
    for (int h = 0; h < HG; ++h) {
        float s  = g_asrc[((size_t)(b*Hh + h0 + h))*Nn + iglob];
        float md = g_maxd[b*Hh + h0 + h];
        float t  = s + md;
        float m  = fmaxf(t, 0.2f*t);                 // lrelu monotone -> row max
        E1i[h] = ex2f_fast((s - m)*LOG2E);
        E2i[h] = ex2f_fast((0.2f*s - m)*LOG2E);
        zacc[h] = 0.f;
    }

    const float4* arow  = (const float4*)(adj + ((size_t)b*Nn + iglob)*Nn);
    const float*  whg   = g_Wh + ((size_t)b*Hh + h0)*Nn*Oo;
    const float*  adstb = g_adst + ((size_t)b*Hh + h0)*Nn;

    // ---- prologue ----
    // wh chunk 0 -> wh[0] via cp.async (group 0)
    #pragma unroll
    for (int r = 0; r < 2; ++r) {
        int q = tid + r*256;                 // 0..511
        int h = q >> 7, k = (q >> 3) & 15, ng = q & 7;
        cp_async16(wh_u32 + (uint32_t)(h*640 + k*40 + ng*4)*4u,
                   whg + ((size_t)h*Nn + k)*Oo + ng*4);
    }
    asm volatile("cp.async.commit_group;" ::: "memory");

    // ej chunk 0 -> ej[0]; dlv = adst(chunk 1) prefetch
    float dlv = 0.f;
    if (tid < 64) {
        float dl = adstb[(size_t)eh*Nn + ej] * LOG2E;
        ej_sm[eh*32 + ej*2 + 0] = ex2f_fast(dl);
        ej_sm[eh*32 + ej*2 + 1] = ex2f_fast(0.2f*dl);
        dlv = adstb[(size_t)eh*Nn + KC + ej] * LOG2E;
    }
    float4 adjv = arow[j4];          // chunk-0 adj

    float acc[2][4][4];
    #pragma unroll
    for (int m = 0; m < 2; ++m)
        #pragma unroll
        for (int nt = 0; nt < 4; ++nt)
            #pragma unroll
            for (int r = 0; r < 4; ++r) acc[m][nt][r] = 0.f;

    __syncthreads();                 // ej[0] visible

    for (int c = 0; c < NCH; ++c) {
        const int buf = c & 1;
        const int jb  = c*KC + j4*4;

        // ======== phase A ========
        // stage ej(c+1) -> ej[buf^1]
        if (c + 1 < NCH && tid < 64) {
            ej_sm[(buf^1)*128 + eh*32 + ej*2 + 0] = ex2f_fast(dlv);
            ej_sm[(buf^1)*128 + eh*32 + ej*2 + 1] = ex2f_fast(0.2f*dlv);
        }

        // masks (shared across the 4 heads)
        float msk[4];
        msk[0] = (adjv.x > 0.f || (jb + 0) == iglob) ? 1.f : 0.f;
        msk[1] = (adjv.y > 0.f || (jb + 1) == iglob) ? 1.f : 0.f;
        msk[2] = (adjv.z > 0.f || (jb + 2) == iglob) ? 1.f : 0.f;
        msk[3] = (adjv.w > 0.f || (jb + 3) == iglob) ? 1.f : 0.f;

        // p-gen for 4 heads -> p[buf]
        #pragma unroll
        for (int h = 0; h < HG; ++h) {
            const float4* ejp = (const float4*)(ej_sm + buf*128 + h*32 + j4*8);
            float4 ea = ejp[0];   // (e1_j0,e2_j0,e1_j1,e2_j1)
            float4 eb = ejp[1];
            float w0 = fmaxf(E1i[h]*ea.x, E2i[h]*ea.y) * msk[0];
            float w1 = fmaxf(E1i[h]*ea.z, E2i[h]*ea.w) * msk[1];
            float w2 = fmaxf(E1i[h]*eb.x, E2i[h]*eb.y) * msk[2];
            float w3 = fmaxf(E1i[h]*eb.z, E2i[h]*eb.w) * msk[3];
            w0 = tf32_rn(w0); w1 = tf32_rn(w1);
            w2 = tf32_rn(w2); w3 = tf32_rn(w3);
            zacc[h] += (w0 + w1) + (w2 + w3);
            *(float4*)(p_sm + buf*5120 + h*1280 + ith*20 + j4*4) =
                make_float4(w0, w1, w2, w3);
        }

        __syncthreads();             // the ONE barrier per chunk

        // ======== phase B ========
        // issue cp.async wh(c+1) -> wh[buf^1]
        if (c + 1 < NCH) {
            #pragma unroll
            for (int r = 0; r < 2; ++r) {
                int q = tid + r*256;
                int h = q >> 7, k = (q >> 3) & 15, ng = q & 7;
                cp_async16(wh_u32 + (uint32_t)((buf^1)*2560 + h*640 + k*40 + ng*4)*4u,
                           whg + ((size_t)h*Nn + (c+1)*KC + k)*Oo + ng*4);
            }
            asm volatile("cp.async.commit_group;" ::: "memory");
            asm volatile("cp.async.wait_group 1;" ::: "memory");
        } else {
            asm volatile("cp.async.wait_group 0;" ::: "memory");
        }

        // mma: warp (hL, mh) reads p[buf], wh[buf]
        {
            const float* ph = p_sm + buf*5120 + hL*1280 + mh*640;
            const float* wt = wh_sm + buf*2560 + hL*640;
            #pragma unroll
            for (int ks = 0; ks < 2; ++ks) {
                const int k0 = ks*8;
                uint32_t bf[4][2];
                #pragma unroll
                for (int nt = 0; nt < 4; ++nt) {
                    bf[nt][0] = __float_as_uint(wt[(k0 + t4)*40 + nt*8 + g]);
                    bf[nt][1] = __float_as_uint(wt[(k0 + t4 + 4)*40 + nt*8 + g]);
                }
                #pragma unroll
                for (int m = 0; m < 2; ++m) {
                    const float* pa = ph + (m*16 + g)*20 + k0;
                    uint32_t a0 = __float_as_uint(pa[t4]);
                    uint32_t a1 = __float_as_uint(pa[160 + t4]);
                    uint32_t a2 = __float_as_uint(pa[t4 + 4]);
                    uint32_t a3 = __float_as_uint(pa[160 + t4 + 4]);
                    #pragma unroll
                    for (int nt = 0; nt < 4; ++nt) {
                        asm volatile(
                          "mma.sync.aligned.m16n8k8.row.col.f32.tf32.tf32.f32 "
                          "{%0,%1,%2,%3}, {%4,%5,%6,%7}, {%8,%9}, {%0,%1,%2,%3};"
                          : "+f"(acc[m][nt][0]), "+f"(acc[m][nt][1]),
                            "+f"(acc[m][nt][2]), "+f"(acc[m][nt][3])
                          : "r"(a0), "r"(a1), "r"(a2), "r"(a3),
                            "r"(bf[nt][0]), "r"(bf[nt][1]));
                    }
                }
            }
        }

        // prefetches for later chunks
        if (c + 1 < NCH) adjv = arow[(c+1)*4 + j4];
        if (c + 2 < NCH && tid < 64)
            dlv = adstb[(size_t)eh*Nn + (c+2)*KC + ej] * LOG2E;
    }

    // ---- Z reduction across the 4 j4-lanes of each row ----
    #pragma unroll
    for (int h = 0; h < HG; ++h) {
        float z = zacc[h];
        z += __shfl_xor_sync(~0u, z, 1);
        z += __shfl_xor_sync(~0u, z, 2);
        if (j4 == 0) z_sm[h*64 + ith] = z;
    }
    __syncthreads();

    // ---- epilogue: normalize, relu, store ----
    {
        float* ob = out + ((size_t)b*Nn + i0 + mh*32)*(Hh*Oo) + (h0 + hL)*Oo;
        #pragma unroll
        for (int m = 0; m < 2; ++m) {
            int r0 = m*16 + g;
            float zi0 = 1.f / z_sm[hL*64 + mh*32 + r0];
            float zi1 = 1.f / z_sm[hL*64 + mh*32 + r0 + 8];
            #pragma unroll
            for (int nt = 0; nt < 4; ++nt) {
                int o = nt*8 + 2*t4;
                float2 v0, v1;
                v0.x = fmaxf(acc[m][nt][0]*zi0, 0.f);
                v0.y = fmaxf(acc[m][nt][1]*zi0, 0.f);
                v1.x = fmaxf(acc[m][nt][2]*zi1, 0.f);
                v1.y = fmaxf(acc[m][nt][3]*zi1, 0.f);
                *(float2*)(ob + (size_t)r0*(Hh*Oo) + o)       = v0;
                *(float2*)(ob + (size_t)(r0 + 8)*(Hh*Oo) + o) = v1;
            }
        }
    }
}

// ============================================================================
extern "C" void kernel_launch(void* const* d_in, const int* in_sizes, int n_in,
                              void* d_out, int out_size)
{
    (void)in_sizes; (void)n_in; (void)out_size;
    const float* x     = (const float*)d_in[0];
    const float* adj   = (const float*)d_in[1];
    const float* W     = (const float*)d_in[2];
    const float* a_src = (const float*)d_in[3];
    const float* a_dst = (const float*)d_in[4];
    float* out = (float*)d_out;

    wh_kernel<<<dim3(Nn/32, Hh, Bb), 256>>>(x, W, a_src, a_dst);
    maxd_kernel<<<Bb*Hh, 256>>>();

    static const int smem_bytes = 63488;
    cudaFuncSetAttribute(gat_mma, cudaFuncAttributeMaxDynamicSharedMemorySize,
                         smem_bytes);
    gat_mma<<<dim3(Nn/BI, Hh/HG, Bb), 256, smem_bytes>>>(adj, out);
}

// round 9
// speedup vs baseline: 1.1698x; 1.1698x over previous
#include <cuda_runtime.h>
#include <cuda_fp16.h>
#include <cstdint>

#define Bb   4
#define Nn   2048
#define Hh   8
#define HG   4            // heads per CTA in gat_mma
#define IN_D 128
#define Oo   32
#define LOG2E 1.44269504f

#define BI   64           // rows per CTA (MMA M)
#define KC   16           // j per chunk (one m16n8k16 K-step)
#define NCH  (Nn/KC)      // 128 chunks

// ---------------- scratch (device globals) ----------------------------------
__device__ __half g_WhT[(size_t)Bb*Hh*Oo*Nn];   // [b][h][o][n], fp16
__device__ float  g_asrc[(size_t)Bb*Hh*Nn];
__device__ float  g_adst[(size_t)Bb*Hh*Nn];
__device__ float  g_maxd[Bb*Hh];

__device__ __forceinline__ float ex2f_fast(float x) {
    float r; asm("ex2.approx.ftz.f32 %0, %1;" : "=f"(r) : "f"(x)); return r;
}
// pack two floats to fp16x2: lo = lo_f, hi = hi_f
__device__ __forceinline__ uint32_t f2h2(float hi_f, float lo_f) {
    uint32_t r;
    asm("cvt.rn.f16x2.f32 %0, %1, %2;" : "=r"(r) : "f"(hi_f), "f"(lo_f));
    return r;
}
__device__ __forceinline__ void cp_async16(uint32_t dst, const void* src) {
    asm volatile("cp.async.cg.shared.global [%0], [%1], 16;"
                 :: "r"(dst), "l"(src));
}

// ============================================================================
// Kernel 1: WhT[b][h][o][n] fp16 + alpha_src/alpha_dst (fp32)
// grid (Nn/32, Hh, Bb) = 2048 CTAs, 256 threads, one head per CTA.
// ============================================================================
__global__ __launch_bounds__(256, 4) void wh_kernel(
    const float* __restrict__ x, const float* __restrict__ W,
    const float* __restrict__ a_src, const float* __restrict__ a_dst)
{
    __shared__ __align__(16) float x_sm[32][IN_D];      // 16 KB
    __shared__ __align__(16) float w_sm[IN_D * Oo];     // 16 KB (reused: 32x33 transpose)

    const int b   = blockIdx.z;
    const int h   = blockIdx.y;
    const int n0  = blockIdx.x * 32;
    const int tid = threadIdx.x;
    const int lane = tid & 31;       // = o
    const int wq   = tid >> 5;       // warp -> 4 rows

    {   // x tile
        const float4* xg = (const float4*)(x + ((size_t)b*Nn + n0)*IN_D);
        float4* xs = (float4*)&x_sm[0][0];
        #pragma unroll
        for (int k = 0; k < 4; ++k) xs[tid + k*256] = xg[tid + k*256];
    }
    {   // W[h]
        const float4* wg = (const float4*)(W + (size_t)h*IN_D*Oo);
        float4* ws = (float4*)w_sm;
        #pragma unroll
        for (int k = 0; k < 4; ++k) ws[tid + k*256] = wg[tid + k*256];
    }
    __syncthreads();

    float acc[4] = {0.f, 0.f, 0.f, 0.f};
    #pragma unroll 8
    for (int f4 = 0; f4 < IN_D/4; ++f4) {
        float4 xv[4];
        #pragma unroll
        for (int r = 0; r < 4; ++r)
            xv[r] = ((const float4*)&x_sm[wq*4 + r][0])[f4];
        #pragma unroll
        for (int u = 0; u < 4; ++u) {
            float wv = w_sm[(f4*4 + u)*Oo + lane];
            acc[0] += (u==0?xv[0].x:u==1?xv[0].y:u==2?xv[0].z:xv[0].w) * wv;
            acc[1] += (u==0?xv[1].x:u==1?xv[1].y:u==2?xv[1].z:xv[1].w) * wv;
            acc[2] += (u==0?xv[2].x:u==1?xv[2].y:u==2?xv[2].z:xv[2].w) * wv;
            acc[3] += (u==0?xv[3].x:u==1?xv[3].y:u==2?xv[3].z:xv[3].w) * wv;
        }
    }

    const float asv = a_src[h*Oo + lane];
    const float adv = a_dst[h*Oo + lane];
    #pragma unroll
    for (int r = 0; r < 4; ++r) {
        int n = n0 + wq*4 + r;
        float ps = acc[r] * asv;
        float pd = acc[r] * adv;
        #pragma unroll
        for (int s = 16; s > 0; s >>= 1) {
            ps += __shfl_xor_sync(~0u, ps, s);
            pd += __shfl_xor_sync(~0u, pd, s);
        }
        if (lane == 0) {
            g_asrc[((size_t)b*Hh + h)*Nn + n] = ps;
            g_adst[((size_t)b*Hh + h)*Nn + n] = pd;
        }
    }

    // transpose via w_sm overlay (everyone done reading w_sm)
    __syncthreads();
    #pragma unroll
    for (int r = 0; r < 4; ++r)
        w_sm[(wq*4 + r)*33 + lane] = acc[r];
    __syncthreads();

    // WhT half store: [o][n], thread writes 4 n-halves (8B), coalesced
    {
        int o  = tid >> 3;
        int ng = tid & 7;
        float v0 = w_sm[(ng*4 + 0)*33 + o];
        float v1 = w_sm[(ng*4 + 1)*33 + o];
        float v2 = w_sm[(ng*4 + 2)*33 + o];
        float v3 = w_sm[(ng*4 + 3)*33 + o];
        uint2 pk;
        pk.x = f2h2(v1, v0);
        pk.y = f2h2(v3, v2);
        *(uint2*)(g_WhT + (((size_t)b*Hh + h)*Oo + o)*Nn + n0 + ng*4) = pk;
    }
}

// ============================================================================
// Kernel 2: per-(b,h) max of alpha_dst
// ============================================================================
__global__ __launch_bounds__(256) void maxd_kernel()
{
    const int bh  = blockIdx.x;
    const int tid = threadIdx.x;
    float m = -1e30f;
    for (int n = tid; n < Nn; n += 256)
        m = fmaxf(m, g_adst[(size_t)bh*Nn + n]);
    __shared__ float red[256];
    red[tid] = m;
    __syncthreads();
    for (int s = 128; s > 0; s >>= 1) {
        if (tid < s) red[tid] = fmaxf(red[tid], red[tid + s]);
        __syncthreads();
    }
    if (tid == 0) g_maxd[bh] = red[0];
}

// ============================================================================
// Kernel 3: fused masked-softmax + AV via mma.sync.m16n8k16.f16 (fp32 accum)
// grid (32, 2, 4) = 256 CTAs; 256 threads; 4 heads/CTA; 2 CTAs/SM.
// Single __syncthreads per chunk (phase A: ej+p-gen; phase B: cp.async+mma).
// SMEM (dynamic, 38912 B), fp16 rows padded to 48 B (conflict-free frags):
//   p_sm  half [2][4][64][24]   bytes 0..24575
//   wh_sm half [2][4][32][24]   bytes 24576..36863   ([o][k] rows)
//   ej_sm f32  [2][4][16][2]    bytes 36864..37887
//   z_sm  f32  [4][64]          bytes 37888..38911
// ============================================================================
__global__ __launch_bounds__(256, 2) void gat_mma(const float* __restrict__ adj,
                                                  float* __restrict__ out)
{
    extern __shared__ char smraw[];
    __half* p_sm  = (__half*)smraw;                  // halves, stride 24
    __half* wh_sm = (__half*)(smraw + 24576);        // halves, stride 24
    float*  ej_sm = (float*)(smraw + 36864);
    float*  z_sm  = (float*)(smraw + 37888);

    const int tid  = threadIdx.x;
    const int lane = tid & 31;
    const int wid  = tid >> 5;       // 0..7
    const int hL   = wid >> 1;       // local mma head 0..3
    const int mh   = wid & 1;        // row half
    const int b    = blockIdx.z;
    const int h0   = blockIdx.y * HG;
    const int i0   = blockIdx.x * BI;
    const int ith  = tid >> 2;       // p-gen row 0..63
    const int j4   = tid & 3;        // p-gen j-quad
    const int iglob = i0 + ith;
    const int g  = lane >> 2;
    const int t4 = lane & 3;
    const int eh = tid >> 4;         // ej-stage head (tid<64)
    const int ej = tid & 15;         // ej-stage j
    // wh cp.async mapping: 1 x 16B per thread per chunk
    const int sh = tid >> 6;         // head 0..3
    const int so = (tid >> 1) & 31;  // o-row
    const int sk = tid & 1;          // 16B half-row

    const uint32_t wh_u32 = (uint32_t)__cvta_generic_to_shared(wh_sm);

    // per-(h,i) hoisted exponentials: w = max(E1i*E1j, E2i*E2j) * mask
    float E1i[HG], E2i[HG], zacc[HG];
    #pragma unroll
    for (int h = 0; h < HG; ++h) {
        float s  = g_asrc[((size_t)(b*Hh + h0 + h))*Nn + iglob];
        float md = g_maxd[b*Hh + h0 + h];
        float t  = s + md;
        float m  = fmaxf(t, 0.2f*t);                 // lrelu monotone -> row max
        E1i[h] = ex2f_fast((s - m)*LOG2E);
        E2i[h] = ex2f_fast((0.2f*s - m)*LOG2E);
        zacc[h] = 0.f;
    }

    const float4*  arow  = (const float4*)(adj + ((size_t)b*Nn + iglob)*Nn);
    const __half*  whtg  = g_WhT + (((size_t)b*Hh + h0)*Oo)*Nn;
    const float*   adstb = g_adst + ((size_t)b*Hh + h0)*Nn;

    // ---- prologue: cp.async wh chunk 0 -> buf 0 ----
    cp_async16(wh_u32 + (uint32_t)(sh*1536 + so*48 + sk*16),
               whtg + ((size_t)sh*Oo + so)*Nn + sk*8);
    asm volatile("cp.async.commit_group;" ::: "memory");

    float dlv = 0.f;
    if (tid < 64) {
        float dl = adstb[(size_t)eh*Nn + ej] * LOG2E;
        ej_sm[eh*32 + ej*2 + 0] = ex2f_fast(dl);
        ej_sm[eh*32 + ej*2 + 1] = ex2f_fast(0.2f*dl);
        dlv = adstb[(size_t)eh*Nn + KC + ej] * LOG2E;
    }
    float4 adjv = arow[j4];          // chunk-0 adj

    float acc[2][4][4];
    #pragma unroll
    for (int m = 0; m < 2; ++m)
        #pragma unroll
        for (int nt = 0; nt < 4; ++nt)
            #pragma unroll
            for (int r = 0; r < 4; ++r) acc[m][nt][r] = 0.f;

    __syncthreads();                 // ej[0] visible

    for (int c = 0; c < NCH; ++c) {
        const int buf = c & 1;
        const int jb  = c*KC + j4*4;

        // ======== phase A ========
        if (c + 1 < NCH && tid < 64) {
            ej_sm[(buf^1)*128 + eh*32 + ej*2 + 0] = ex2f_fast(dlv);
            ej_sm[(buf^1)*128 + eh*32 + ej*2 + 1] = ex2f_fast(0.2f*dlv);
        }

        float msk[4];
        msk[0] = (adjv.x > 0.f || (jb + 0) == iglob) ? 1.f : 0.f;
        msk[1] = (adjv.y > 0.f || (jb + 1) == iglob) ? 1.f : 0.f;
        msk[2] = (adjv.z > 0.f || (jb + 2) == iglob) ? 1.f : 0.f;
        msk[3] = (adjv.w > 0.f || (jb + 3) == iglob) ? 1.f : 0.f;

        // p-gen for 4 heads -> p[buf] (fp16)
        #pragma unroll
        for (int h = 0; h < HG; ++h) {
            const float4* ejp = (const float4*)(ej_sm + buf*128 + h*32 + j4*8);
            float4 ea = ejp[0];
            float4 eb = ejp[1];
            float w0 = fmaxf(E1i[h]*ea.x, E2i[h]*ea.y) * msk[0];
            float w1 = fmaxf(E1i[h]*ea.z, E2i[h]*ea.w) * msk[1];
            float w2 = fmaxf(E1i[h]*eb.x, E2i[h]*eb.y) * msk[2];
            float w3 = fmaxf(E1i[h]*eb.z, E2i[h]*eb.w) * msk[3];
            zacc[h] += (w0 + w1) + (w2 + w3);
            uint2 pk;
            pk.x = f2h2(w1, w0);
            pk.y = f2h2(w3, w2);
            *(uint2*)((char*)p_sm + buf*12288 + h*3072 + ith*48 + j4*8) = pk;
        }

        __syncthreads();             // the ONE barrier per chunk

        // ======== phase B ========
        if (c + 1 < NCH) {
            cp_async16(wh_u32 + (uint32_t)((buf^1)*6144 + sh*1536 + so*48 + sk*16),
                       whtg + ((size_t)sh*Oo + so)*Nn + (c+1)*KC + sk*8);
            asm volatile("cp.async.commit_group;" ::: "memory");
            asm volatile("cp.async.wait_group 1;" ::: "memory");
        } else {
            asm volatile("cp.async.wait_group 0;" ::: "memory");
        }

        // mma: warp (hL, mh) reads p[buf], wh[buf]; one m16n8k16 K-step
        {
            const __half* ph = (const __half*)((char*)p_sm + buf*12288 + hL*3072
                                               + mh*32*48);
            const __half* wt = (const __half*)((char*)wh_sm + buf*6144 + hL*1536);
            uint32_t bf[4][2];
            #pragma unroll
            for (int nt = 0; nt < 4; ++nt) {
                const __half* br = wt + (nt*8 + g)*24;
                bf[nt][0] = *(const uint32_t*)(br + 2*t4);
                bf[nt][1] = *(const uint32_t*)(br + 2*t4 + 8);
            }
            #pragma unroll
            for (int m = 0; m < 2; ++m) {
                const __half* pa = ph + (m*16 + g)*24;
                const __half* pa8 = pa + 8*24;
                uint32_t a0 = *(const uint32_t*)(pa  + 2*t4);
                uint32_t a1 = *(const uint32_t*)(pa8 + 2*t4);
                uint32_t a2 = *(const uint32_t*)(pa  + 2*t4 + 8);
                uint32_t a3 = *(const uint32_t*)(pa8 + 2*t4 + 8);
                #pragma unroll
                for (int nt = 0; nt < 4; ++nt) {
                    asm volatile(
                      "mma.sync.aligned.m16n8k16.row.col.f32.f16.f16.f32 "
                      "{%0,%1,%2,%3}, {%4,%5,%6,%7}, {%8,%9}, {%0,%1,%2,%3};"
                      : "+f"(acc[m][nt][0]), "+f"(acc[m][nt][1]),
                        "+f"(acc[m][nt][2]), "+f"(acc[m][nt][3])
                      : "r"(a0), "r"(a1), "r"(a2), "r"(a3),
                        "r"(bf[nt][0]), "r"(bf[nt][1]));
                }
            }
        }

        // prefetches
        if (c + 1 < NCH) adjv = arow[(c+1)*4 + j4];
        if (c + 2 < NCH && tid < 64)
            dlv = adstb[(size_t)eh*Nn + (c+2)*KC + ej] * LOG2E;
    }

    // ---- Z reduction across the 4 j4-lanes of each row ----
    #pragma unroll
    for (int h = 0; h < HG; ++h) {
        float z = zacc[h];
        z += __shfl_xor_sync(~0u, z, 1);
        z += __shfl_xor_sync(~0u, z, 2);
        if (j4 == 0) z_sm[h*64 + ith] = z;
    }
    __syncthreads();

    // ---- epilogue: normalize, relu, store ----
    {
        float* ob = out + ((size_t)b*Nn + i0 + mh*32)*(Hh*Oo) + (h0 + hL)*Oo;
        #pragma unroll
        for (int m = 0; m < 2; ++m) {
            int r0 = m*16 + g;
            float zi0 = 1.f / z_sm[hL*64 + mh*32 + r0];
            float zi1 = 1.f / z_sm[hL*64 + mh*32 + r0 + 8];
            #pragma unroll
            for (int nt = 0; nt < 4; ++nt) {
                int o = nt*8 + 2*t4;
                float2 v0, v1;
                v0.x = fmaxf(acc[m][nt][0]*zi0, 0.f);
                v0.y = fmaxf(acc[m][nt][1]*zi0, 0.f);
                v1.x = fmaxf(acc[m][nt][2]*zi1, 0.f);
                v1.y = fmaxf(acc[m][nt][3]*zi1, 0.f);
                *(float2*)(ob + (size_t)r0*(Hh*Oo) + o)       = v0;
                *(float2*)(ob + (size_t)(r0 + 8)*(Hh*Oo) + o) = v1;
            }
        }
    }
}

// ============================================================================
extern "C" void kernel_launch(void* const* d_in, const int* in_sizes, int n_in,
                              void* d_out, int out_size)
{
    (void)in_sizes; (void)n_in; (void)out_size;
    const float* x     = (const float*)d_in[0];
    const float* adj   = (const float*)d_in[1];
    const float* W     = (const float*)d_in[2];
    const float* a_src = (const float*)d_in[3];
    const float* a_dst = (const float*)d_in[4];
    float* out = (float*)d_out;

    wh_kernel<<<dim3(Nn/32, Hh, Bb), 256>>>(x, W, a_src, a_dst);
    maxd_kernel<<<Bb*Hh, 256>>>();

    static const int smem_bytes = 38912;
    cudaFuncSetAttribute(gat_mma, cudaFuncAttributeMaxDynamicSharedMemorySize,
                         smem_bytes);
    gat_mma<<<dim3(Nn/BI, Hh/HG, Bb), 256, smem_bytes>>>(adj, out);
}

// round 10
// speedup vs baseline: 1.2979x; 1.1095x over previous
#include <cuda_runtime.h>
#include <cuda_fp16.h>
#include <cstdint>

#define Bb   4
#define Nn   2048
#define Hh   8
#define HG   4            // heads per CTA in gat_mma
#define IN_D 128
#define Oo   32
#define LOG2E 1.44269504f

#define BI   64           // rows per CTA (MMA M)
#define KC   16           // j per chunk (one m16n8k16 K-step)
#define NCH  (Nn/KC)      // 128 chunks

// ---------------- scratch (device globals) ----------------------------------
__device__ __half g_WhT[(size_t)Bb*Hh*Oo*Nn];   // [b][h][o][n], fp16
__device__ float  g_asrc[(size_t)Bb*Hh*Nn];
__device__ float  g_adst[(size_t)Bb*Hh*Nn];
__device__ float  g_maxd[Bb*Hh];

__device__ __forceinline__ float ex2f_fast(float x) {
    float r; asm("ex2.approx.ftz.f32 %0, %1;" : "=f"(r) : "f"(x)); return r;
}
// pack two floats to fp16x2: lo half = lo_f, hi half = hi_f
__device__ __forceinline__ uint32_t f2h2(float hi_f, float lo_f) {
    uint32_t r;
    asm("cvt.rn.f16x2.f32 %0, %1, %2;" : "=r"(r) : "f"(hi_f), "f"(lo_f));
    return r;
}
__device__ __forceinline__ __half2 u2h2(uint32_t u) {
    __half2 h; *(uint32_t*)&h = u; return h;
}
__device__ __forceinline__ uint32_t h2u2(__half2 h) {
    return *(uint32_t*)&h;
}
__device__ __forceinline__ void cp_async16(uint32_t dst, const void* src) {
    asm volatile("cp.async.cg.shared.global [%0], [%1], 16;"
                 :: "r"(dst), "l"(src));
}

// ============================================================================
// Kernel 1: WhT[b][h][o][n] fp16 + alpha_src/alpha_dst (fp32)
// grid (Nn/32, Hh, Bb) = 2048 CTAs, 256 threads, one head per CTA.
// ============================================================================
__global__ __launch_bounds__(256, 4) void wh_kernel(
    const float* __restrict__ x, const float* __restrict__ W,
    const float* __restrict__ a_src, const float* __restrict__ a_dst)
{
    __shared__ __align__(16) float x_sm[32][IN_D];      // 16 KB
    __shared__ __align__(16) float w_sm[IN_D * Oo];     // 16 KB (reused: 32x33 transpose)

    const int b   = blockIdx.z;
    const int h   = blockIdx.y;
    const int n0  = blockIdx.x * 32;
    const int tid = threadIdx.x;
    const int lane = tid & 31;       // = o
    const int wq   = tid >> 5;       // warp -> 4 rows

    {   // x tile
        const float4* xg = (const float4*)(x + ((size_t)b*Nn + n0)*IN_D);
        float4* xs = (float4*)&x_sm[0][0];
        #pragma unroll
        for (int k = 0; k < 4; ++k) xs[tid + k*256] = xg[tid + k*256];
    }
    {   // W[h]
        const float4* wg = (const float4*)(W + (size_t)h*IN_D*Oo);
        float4* ws = (float4*)w_sm;
        #pragma unroll
        for (int k = 0; k < 4; ++k) ws[tid + k*256] = wg[tid + k*256];
    }
    __syncthreads();

    float acc[4] = {0.f, 0.f, 0.f, 0.f};
    #pragma unroll 8
    for (int f4 = 0; f4 < IN_D/4; ++f4) {
        float4 xv[4];
        #pragma unroll
        for (int r = 0; r < 4; ++r)
            xv[r] = ((const float4*)&x_sm[wq*4 + r][0])[f4];
        #pragma unroll
        for (int u = 0; u < 4; ++u) {
            float wv = w_sm[(f4*4 + u)*Oo + lane];
            acc[0] += (u==0?xv[0].x:u==1?xv[0].y:u==2?xv[0].z:xv[0].w) * wv;
            acc[1] += (u==0?xv[1].x:u==1?xv[1].y:u==2?xv[1].z:xv[1].w) * wv;
            acc[2] += (u==0?xv[2].x:u==1?xv[2].y:u==2?xv[2].z:xv[2].w) * wv;
            acc[3] += (u==0?xv[3].x:u==1?xv[3].y:u==2?xv[3].z:xv[3].w) * wv;
        }
    }

    const float asv = a_src[h*Oo + lane];
    const float adv = a_dst[h*Oo + lane];
    #pragma unroll
    for (int r = 0; r < 4; ++r) {
        int n = n0 + wq*4 + r;
        float ps = acc[r] * asv;
        float pd = acc[r] * adv;
        #pragma unroll
        for (int s = 16; s > 0; s >>= 1) {
            ps += __shfl_xor_sync(~0u, ps, s);
            pd += __shfl_xor_sync(~0u, pd, s);
        }
        if (lane == 0) {
            g_asrc[((size_t)b*Hh + h)*Nn + n] = ps;
            g_adst[((size_t)b*Hh + h)*Nn + n] = pd;
        }
    }

    // transpose via w_sm overlay (everyone done reading w_sm)
    __syncthreads();
    #pragma unroll
    for (int r = 0; r < 4; ++r)
        w_sm[(wq*4 + r)*33 + lane] = acc[r];
    __syncthreads();

    // WhT half store: [o][n], thread writes 4 n-halves (8B), coalesced
    {
        int o  = tid >> 3;
        int ng = tid & 7;
        float v0 = w_sm[(ng*4 + 0)*33 + o];
        float v1 = w_sm[(ng*4 + 1)*33 + o];
        float v2 = w_sm[(ng*4 + 2)*33 + o];
        float v3 = w_sm[(ng*4 + 3)*33 + o];
        uint2 pk;
        pk.x = f2h2(v1, v0);
        pk.y = f2h2(v3, v2);
        *(uint2*)(g_WhT + (((size_t)b*Hh + h)*Oo + o)*Nn + n0 + ng*4) = pk;
    }
}

// ============================================================================
// Kernel 2: per-(b,h) max of alpha_dst
// ============================================================================
__global__ __launch_bounds__(256) void maxd_kernel()
{
    const int bh  = blockIdx.x;
    const int tid = threadIdx.x;
    float m = -1e30f;
    for (int n = tid; n < Nn; n += 256)
        m = fmaxf(m, g_adst[(size_t)bh*Nn + n]);
    __shared__ float red[256];
    red[tid] = m;
    __syncthreads();
    for (int s = 128; s > 0; s >>= 1) {
        if (tid < s) red[tid] = fmaxf(red[tid], red[tid + s]);
        __syncthreads();
    }
    if (tid == 0) g_maxd[bh] = red[0];
}

// ============================================================================
// Kernel 3: fused masked-softmax + AV via mma.sync.m16n8k16.f16 (fp32 accum)
// grid (32, 2, 4) = 256 CTAs; 256 threads; 4 heads/CTA; 2 CTAs/SM.
// half2 SIMD p-gen; Z accumulated by an extra ones-column MMA (no scalar Z).
// Single __syncthreads per chunk.
// SMEM (dynamic, 37376 B):
//   p_sm  half [2][4][64][24]   bytes 0..24575
//   wh_sm half [2][4][32][24]   bytes 24576..36863   ([o][k] rows)
//   ej_sm      [2][4][4][16B]   bytes 36864..37375   {e1_01,e1_23,e2_01,e2_23}
// ============================================================================
__global__ __launch_bounds__(256, 2) void gat_mma(const float* __restrict__ adj,
                                                  float* __restrict__ out)
{
    extern __shared__ char smraw[];
    __half* p_sm  = (__half*)smraw;                  // halves, row stride 48 B
    __half* wh_sm = (__half*)(smraw + 24576);        // halves, row stride 48 B
    char*   ej_sm = smraw + 36864;

    const int tid  = threadIdx.x;
    const int lane = tid & 31;
    const int wid  = tid >> 5;       // 0..7
    const int hL   = wid >> 1;       // local mma head 0..3
    const int mh   = wid & 1;        // row half
    const int b    = blockIdx.z;
    const int h0   = blockIdx.y * HG;
    const int i0   = blockIdx.x * BI;
    const int ith  = tid >> 2;       // p-gen row 0..63
    const int j4   = tid & 3;        // p-gen j-quad
    const int iglob = i0 + ith;
    const int g  = lane >> 2;
    const int t4 = lane & 3;
    // ej staging (tid<32): thread -> (head, j-pair)
    const int zh = tid >> 3;         // head 0..3
    const int zp = tid & 7;          // j-pair 0..7
    // wh cp.async mapping: 1 x 16B per thread per chunk
    const int sh = tid >> 6;         // head 0..3
    const int so = (tid >> 1) & 31;  // o-row
    const int sk = tid & 1;          // 16B half-row

    const uint32_t wh_u32 = (uint32_t)__cvta_generic_to_shared(wh_sm);

    // per-(h,i) hoisted exponentials as half2 broadcasts
    __half2 E1i2[HG], E2i2[HG];
    #pragma unroll
    for (int h = 0; h < HG; ++h) {
        float s  = g_asrc[((size_t)(b*Hh + h0 + h))*Nn + iglob];
        float md = g_maxd[b*Hh + h0 + h];
        float t  = s + md;
        float m  = fmaxf(t, 0.2f*t);                 // lrelu monotone -> row max
        E1i2[h] = __float2half2_rn(ex2f_fast((s - m)*LOG2E));
        E2i2[h] = __float2half2_rn(ex2f_fast((0.2f*s - m)*LOG2E));
    }

    const float4*  arow  = (const float4*)(adj + ((size_t)b*Nn + iglob)*Nn);
    const __half*  whtg  = g_WhT + (((size_t)b*Hh + h0)*Oo)*Nn;
    const float*   adstb = g_adst + ((size_t)b*Hh + h0)*Nn;

    // ---- prologue: cp.async wh chunk 0 -> buf 0 ----
    cp_async16(wh_u32 + (uint32_t)(sh*1536 + so*48 + sk*16),
               whtg + ((size_t)sh*Oo + so)*Nn + sk*8);
    asm volatile("cp.async.commit_group;" ::: "memory");

    // ej chunk 0 -> buf 0; prefetch chunk-1 dl pair
    float2 dlv = make_float2(0.f, 0.f);
    if (tid < 32) {
        float2 d0 = *(const float2*)(adstb + (size_t)zh*Nn + zp*2);
        float a0 = d0.x*LOG2E, a1 = d0.y*LOG2E;
        uint32_t e1 = f2h2(ex2f_fast(a1), ex2f_fast(a0));
        uint32_t e2 = f2h2(ex2f_fast(0.2f*a1), ex2f_fast(0.2f*a0));
        int base = zh*64 + (zp>>1)*16 + (zp&1)*4;
        *(uint32_t*)(ej_sm + base)     = e1;
        *(uint32_t*)(ej_sm + base + 8) = e2;
        dlv = *(const float2*)(adstb + (size_t)zh*Nn + KC + zp*2);
    }
    float4 adjv = arow[j4];          // chunk-0 adj

    float acc[2][4][4];
    float accz[2][4];
    #pragma unroll
    for (int m = 0; m < 2; ++m) {
        #pragma unroll
        for (int nt = 0; nt < 4; ++nt)
            #pragma unroll
            for (int r = 0; r < 4; ++r) acc[m][nt][r] = 0.f;
        #pragma unroll
        for (int r = 0; r < 4; ++r) accz[m][r] = 0.f;
    }
    // ones-column B fragment (constant): lanes with g==0 hold column n=0
    const uint32_t bones = (g == 0) ? 0x3C003C00u : 0u;

    __syncthreads();                 // ej[0] visible

    for (int c = 0; c < NCH; ++c) {
        const int buf = c & 1;
        const int jb  = c*KC + j4*4;

        // ======== phase A ========
        // stage ej(c+1) -> ej[buf^1]
        if (c + 1 < NCH && tid < 32) {
            float a0 = dlv.x*LOG2E, a1 = dlv.y*LOG2E;
            uint32_t e1 = f2h2(ex2f_fast(a1), ex2f_fast(a0));
            uint32_t e2 = f2h2(ex2f_fast(0.2f*a1), ex2f_fast(0.2f*a0));
            int base = (buf^1)*256 + zh*64 + (zp>>1)*16 + (zp&1)*4;
            *(uint32_t*)(ej_sm + base)     = e1;
            *(uint32_t*)(ej_sm + base + 8) = e2;
        }

        // masks as half2 pairs (shared across the 4 heads)
        float m0 = (adjv.x > 0.f || (jb + 0) == iglob) ? 1.f : 0.f;
        float m1 = (adjv.y > 0.f || (jb + 1) == iglob) ? 1.f : 0.f;
        float m2 = (adjv.z > 0.f || (jb + 2) == iglob) ? 1.f : 0.f;
        float m3 = (adjv.w > 0.f || (jb + 3) == iglob) ? 1.f : 0.f;
        __half2 msk01 = u2h2(f2h2(m1, m0));
        __half2 msk23 = u2h2(f2h2(m3, m2));

        // p-gen for 4 heads -> p[buf] (half2 SIMD)
        #pragma unroll
        for (int h = 0; h < HG; ++h) {
            uint4 e = *(const uint4*)(ej_sm + buf*256 + h*64 + j4*16);
            __half2 w01 = __hmax2(__hmul2(E1i2[h], u2h2(e.x)),
                                  __hmul2(E2i2[h], u2h2(e.z)));
            __half2 w23 = __hmax2(__hmul2(E1i2[h], u2h2(e.y)),
                                  __hmul2(E2i2[h], u2h2(e.w)));
            w01 = __hmul2(w01, msk01);
            w23 = __hmul2(w23, msk23);
            uint2 pk; pk.x = h2u2(w01); pk.y = h2u2(w23);
            *(uint2*)((char*)p_sm + buf*12288 + h*3072 + ith*48 + j4*8) = pk;
        }

        __syncthreads();             // the ONE barrier per chunk

        // ======== phase B ========
        if (c + 1 < NCH) {
            cp_async16(wh_u32 + (uint32_t)((buf^1)*6144 + sh*1536 + so*48 + sk*16),
                       whtg + ((size_t)sh*Oo + so)*Nn + (c+1)*KC + sk*8);
            asm volatile("cp.async.commit_group;" ::: "memory");
            asm volatile("cp.async.wait_group 1;" ::: "memory");
        } else {
            asm volatile("cp.async.wait_group 0;" ::: "memory");
        }

        // mma: warp (hL, mh) reads p[buf], wh[buf]; one m16n8k16 K-step
        {
            const __half* ph = (const __half*)((char*)p_sm + buf*12288 + hL*3072
                                               + mh*32*48);
            const __half* wt = (const __half*)((char*)wh_sm + buf*6144 + hL*1536);
            uint32_t bf[4][2];
            #pragma unroll
            for (int nt = 0; nt < 4; ++nt) {
                const __half* br = wt + (nt*8 + g)*24;
                bf[nt][0] = *(const uint32_t*)(br + 2*t4);
                bf[nt][1] = *(const uint32_t*)(br + 2*t4 + 8);
            }
            #pragma unroll
            for (int m = 0; m < 2; ++m) {
                const __half* pa = ph + (m*16 + g)*24;
                const __half* pa8 = pa + 8*24;
                uint32_t a0 = *(const uint32_t*)(pa  + 2*t4);
                uint32_t a1 = *(const uint32_t*)(pa8 + 2*t4);
                uint32_t a2 = *(const uint32_t*)(pa  + 2*t4 + 8);
                uint32_t a3 = *(const uint32_t*)(pa8 + 2*t4 + 8);
                #pragma unroll
                for (int nt = 0; nt < 4; ++nt) {
                    asm volatile(
                      "mma.sync.aligned.m16n8k16.row.col.f32.f16.f16.f32 "
                      "{%0,%1,%2,%3}, {%4,%5,%6,%7}, {%8,%9}, {%0,%1,%2,%3};"
                      : "+f"(acc[m][nt][0]), "+f"(acc[m][nt][1]),
                        "+f"(acc[m][nt][2]), "+f"(acc[m][nt][3])
                      : "r"(a0), "r"(a1), "r"(a2), "r"(a3),
                        "r"(bf[nt][0]), "r"(bf[nt][1]));
                }
                // Z accumulation: ones-column B (register constant)
                asm volatile(
                  "mma.sync.aligned.m16n8k16.row.col.f32.f16.f16.f32 "
                  "{%0,%1,%2,%3}, {%4,%5,%6,%7}, {%8,%9}, {%0,%1,%2,%3};"
                  : "+f"(accz[m][0]), "+f"(accz[m][1]),
                    "+f"(accz[m][2]), "+f"(accz[m][3])
                  : "r"(a0), "r"(a1), "r"(a2), "r"(a3),
                    "r"(bones), "r"(bones));
            }
        }

        // prefetches
        if (c + 1 < NCH) adjv = arow[(c+1)*4 + j4];
        if (c + 2 < NCH && tid < 32)
            dlv = *(const float2*)(adstb + (size_t)zh*Nn + (c+2)*KC + zp*2);
    }

    // ---- epilogue: Z broadcast (t4==0 lanes hold column 0), normalize ----
    {
        float* ob = out + ((size_t)b*Nn + i0 + mh*32)*(Hh*Oo) + (h0 + hL)*Oo;
        #pragma unroll
        for (int m = 0; m < 2; ++m) {
            int r0 = m*16 + g;
            float z0 = __shfl_sync(~0u, accz[m][0], lane & ~3);
            float z1 = __shfl_sync(~0u, accz[m][2], lane & ~3);
            float zi0 = 1.f / z0;
            float zi1 = 1.f / z1;
            #pragma unroll
            for (int nt = 0; nt < 4; ++nt) {
                int o = nt*8 + 2*t4;
                float2 v0, v1;
                v0.x = fmaxf(acc[m][nt][0]*zi0, 0.f);
                v0.y = fmaxf(acc[m][nt][1]*zi0, 0.f);
                v1.x = fmaxf(acc[m][nt][2]*zi1, 0.f);
                v1.y = fmaxf(acc[m][nt][3]*zi1, 0.f);
                *(float2*)(ob + (size_t)r0*(Hh*Oo) + o)       = v0;
                *(float2*)(ob + (size_t)(r0 + 8)*(Hh*Oo) + o) = v1;
            }
        }
    }
}

// ============================================================================
extern "C" void kernel_launch(void* const* d_in, const int* in_sizes, int n_in,
                              void* d_out, int out_size)
{
    (void)in_sizes; (void)n_in; (void)out_size;
    const float* x     = (const float*)d_in[0];
    const float* adj   = (const float*)d_in[1];
    const float* W     = (const float*)d_in[2];
    const float* a_src = (const float*)d_in[3];
    const float* a_dst = (const float*)d_in[4];
    float* out = (float*)d_out;

    wh_kernel<<<dim3(Nn/32, Hh, Bb), 256>>>(x, W, a_src, a_dst);
    maxd_kernel<<<Bb*Hh, 256>>>();

    static const int smem_bytes = 37376;
    cudaFuncSetAttribute(gat_mma, cudaFuncAttributeMaxDynamicSharedMemorySize,
                         smem_bytes);
    gat_mma<<<dim3(Nn/BI, Hh/HG, Bb), 256, smem_bytes>>>(adj, out);
}